// round 2
// baseline (speedup 1.0000x reference)
#include <cuda_runtime.h>
#include <cstdint>

// Problem constants (fixed shapes from reference)
static constexpr long long N  = 100000;   // nodes
static constexpr long long E  = 3200000;  // edges
static constexpr long long D  = 256;      // node feat
static constexpr long long De = 32;       // edge feat
static constexpr long long B  = 128;      // graphs

// Output layout (float32 units), concatenation of flattened outputs:
// new_x [N+B, D] | new_edge_index [2, E+N] | new_edge_attribute [E+N, De] | new_batch [N+B]
static constexpr long long OFF_X       = 0;
static constexpr long long OFF_X_ZERO  = OFF_X + N * D;                 // 25,600,000
static constexpr long long OFF_EI      = OFF_X + (N + B) * D;           // 25,632,768
static constexpr long long OFF_EI_R0   = OFF_EI;
static constexpr long long OFF_HEADS   = OFF_EI_R0 + E;                 // 28,832,768
static constexpr long long OFF_EI_R1   = OFF_EI + (E + N);              // 28,932,768
static constexpr long long OFF_TAILS   = OFF_EI_R1 + E;                 // 32,132,768
static constexpr long long OFF_EA      = OFF_EI + 2 * (E + N);          // 32,232,768
static constexpr long long OFF_EA_ZERO = OFF_EA + E * De;               // 134,632,768
static constexpr long long OFF_B       = OFF_EA + (E + N) * De;         // 137,832,768
static constexpr long long OFF_B_AR    = OFF_B + N;                     // end = 137,932,896

// All region offsets are multiples of 4 floats -> 16B aligned. All stores are
// guarded against out_size so a layout mismatch fails soft (rel_err), not IMA.

__global__ void copy4_kernel(const float4* __restrict__ src, float* __restrict__ out,
                             long long dst_off, long long n4, long long out_lim) {
    long long i = (long long)blockIdx.x * blockDim.x + threadIdx.x;
    if (i < n4) {
        long long o = dst_off + 4 * i;
        if (o + 3 < out_lim) ((float4*)(out + o))[0] = src[i];
    }
}

__global__ void zero4_kernel(float* __restrict__ out, long long dst_off,
                             long long n4, long long out_lim) {
    long long i = (long long)blockIdx.x * blockDim.x + threadIdx.x;
    if (i < n4) {
        long long o = dst_off + 4 * i;
        if (o + 3 < out_lim) ((float4*)(out + o))[0] = make_float4(0.f, 0.f, 0.f, 0.f);
    }
}

// int32 -> float32 convert, 4 elements per thread (one 16B load, one 16B store)
__global__ void cvt32_4_kernel(const int4* __restrict__ src, float* __restrict__ out,
                               long long dst_off, long long n4, long long out_lim) {
    long long i = (long long)blockIdx.x * blockDim.x + threadIdx.x;
    if (i < n4) {
        int4 a = src[i];
        long long o = dst_off + 4 * i;
        if (o + 3 < out_lim)
            ((float4*)(out + o))[0] =
                make_float4((float)a.x, (float)a.y, (float)a.z, (float)a.w);
    }
}

// Small fused kernel: heads = arange(N), tails = N + batch, new_batch = batch,
// new_batch tail = arange(B). Reads batch once, writes three regions + tail.
__global__ void vnode_small_kernel(const int4* __restrict__ batch,
                                   float* __restrict__ out, long long out_lim) {
    long long i = (long long)blockIdx.x * blockDim.x + threadIdx.x;
    const long long n4 = N / 4;  // 25000
    if (i < n4) {
        int4 b = batch[i];
        float fi = (float)(4 * i);
        long long oh = OFF_HEADS + 4 * i;
        long long ot = OFF_TAILS + 4 * i;
        long long ob = OFF_B + 4 * i;
        if (oh + 3 < out_lim)
            ((float4*)(out + oh))[0] = make_float4(fi, fi + 1.f, fi + 2.f, fi + 3.f);
        if (ot + 3 < out_lim)
            ((float4*)(out + ot))[0] = make_float4((float)(N + b.x), (float)(N + b.y),
                                                   (float)(N + b.z), (float)(N + b.w));
        if (ob + 3 < out_lim)
            ((float4*)(out + ob))[0] = make_float4((float)b.x, (float)b.y,
                                                   (float)b.z, (float)b.w);
    }
    if (i < B) {
        long long o = OFF_B_AR + i;
        if (o < out_lim) out[o] = (float)i;
    }
}

extern "C" void kernel_launch(void* const* d_in, const int* in_sizes, int n_in,
                              void* d_out, int out_size) {
    const float* x     = (const float*)d_in[0];   // [N, D] f32
    const int*   ei    = (const int*)d_in[1];     // [2, E] int32 (int64 downcast by harness)
    const float* ea    = (const float*)d_in[2];   // [E, De] f32
    const int*   batch = (const int*)d_in[3];     // [N] int32
    float* out = (float*)d_out;
    const long long lim = (long long)out_size;

    const int T = 256;
    auto blocks = [&](long long n) { return (unsigned)((n + T - 1) / T); };

    // 1) new_x: copy x (N*D floats) then zero B*D floats
    {
        long long n4 = N * D / 4;  // 6,400,000
        copy4_kernel<<<blocks(n4), T>>>((const float4*)x, out, OFF_X, n4, lim);
        long long z4 = B * D / 4;  // 8,192
        zero4_kernel<<<blocks(z4), T>>>(out, OFF_X_ZERO, z4, lim);
    }

    // 2) new_edge_index rows: int32 -> f32 convert
    {
        long long n4 = E / 4;  // 800,000
        cvt32_4_kernel<<<blocks(n4), T>>>((const int4*)ei, out, OFF_EI_R0, n4, lim);
        cvt32_4_kernel<<<blocks(n4), T>>>((const int4*)(ei + E), out, OFF_EI_R1, n4, lim);
    }

    // 3) new_edge_attribute: copy E*De floats then zero N*De floats
    {
        long long n4 = E * De / 4;  // 25,600,000
        copy4_kernel<<<blocks(n4), T>>>((const float4*)ea, out, OFF_EA, n4, lim);
        long long z4 = N * De / 4;  // 800,000
        zero4_kernel<<<blocks(z4), T>>>(out, OFF_EA_ZERO, z4, lim);
    }

    // 4) heads/tails/new_batch/arange(B) fused
    {
        long long n4 = N / 4;  // 25,000
        vnode_small_kernel<<<blocks(n4), T>>>((const int4*)batch, out, lim);
    }
}

// round 3
// speedup vs baseline: 1.0592x; 1.0592x over previous
#include <cuda_runtime.h>
#include <cstdint>

// Problem constants (fixed shapes from reference)
static constexpr long long N  = 100000;   // nodes
static constexpr long long E  = 3200000;  // edges
static constexpr long long D  = 256;      // node feat
static constexpr long long De = 32;       // edge feat
static constexpr long long B  = 128;      // graphs

// Output layout (float32 units), concatenation of flattened outputs:
// new_x [N+B, D] | new_edge_index [2, E+N] | new_edge_attribute [E+N, De] | new_batch [N+B]
static constexpr long long OFF_X       = 0;
static constexpr long long OFF_X_ZERO  = OFF_X + N * D;                 // 25,600,000
static constexpr long long OFF_EI      = OFF_X + (N + B) * D;           // 25,632,768
static constexpr long long OFF_EI_R0   = OFF_EI;
static constexpr long long OFF_HEADS   = OFF_EI_R0 + E;                 // 28,832,768
static constexpr long long OFF_EI_R1   = OFF_EI + (E + N);              // 28,932,768
static constexpr long long OFF_TAILS   = OFF_EI_R1 + E;                 // 32,132,768
static constexpr long long OFF_EA      = OFF_EI + 2 * (E + N);          // 32,232,768
static constexpr long long OFF_EA_ZERO = OFF_EA + E * De;               // 134,632,768
static constexpr long long OFF_B       = OFF_EA + (E + N) * De;         // 137,832,768
static constexpr long long OFF_B_AR    = OFF_B + N;                     // 137,932,768
static constexpr long long OFF_END     = OFF_B_AR + B;                  // 137,932,896

// All region boundaries are multiples of 4 floats, so every 16B output chunk
// falls entirely within one region. Single fused kernel over the whole output:
// no inter-kernel gaps, no wave-tail fragmentation. Streaming loads/stores
// (evict-first) since nothing is reused within the launch.

__device__ __forceinline__ float4 ldcs4f(const float4* p) { return __ldcs(p); }
__device__ __forceinline__ int4   ldcs4i(const int4* p)   { return __ldcs(p); }

__global__ void __launch_bounds__(256) vnode_fused_kernel(
    const float* __restrict__ x,      // [N, D] f32
    const int*   __restrict__ ei,     // [2, E] i32
    const float* __restrict__ ea,     // [E, De] f32
    const int*   __restrict__ batch,  // [N] i32
    float* __restrict__ out, long long out_lim)
{
    long long i = (long long)blockIdx.x * blockDim.x + threadIdx.x;
    long long o = 4 * i;  // float offset of this thread's 16B chunk
    if (o + 3 >= out_lim || o + 3 >= OFF_END) return;

    float4 v;

    if (o >= OFF_EA && o < OFF_EA_ZERO) {
        // edge_attribute copy (77% of all chunks)
        v = ldcs4f((const float4*)(ea + (o - OFF_EA)));
    } else if (o < OFF_X_ZERO) {
        // x copy (18.6%)
        v = ldcs4f((const float4*)(x + o));
    } else if (o < OFF_EI) {
        // x virtual-node zeros
        v = make_float4(0.f, 0.f, 0.f, 0.f);
    } else if (o < OFF_HEADS) {
        // edge_index row 0: int -> float
        int4 a = ldcs4i((const int4*)(ei + (o - OFF_EI_R0)));
        v = make_float4((float)a.x, (float)a.y, (float)a.z, (float)a.w);
    } else if (o < OFF_EI_R1) {
        // heads = arange(N)
        float f = (float)(o - OFF_HEADS);
        v = make_float4(f, f + 1.f, f + 2.f, f + 3.f);
    } else if (o < OFF_TAILS) {
        // edge_index row 1: int -> float
        int4 a = ldcs4i((const int4*)(ei + E + (o - OFF_EI_R1)));
        v = make_float4((float)a.x, (float)a.y, (float)a.z, (float)a.w);
    } else if (o < OFF_EA) {
        // tails = N + batch
        int4 b = ldcs4i((const int4*)(batch + (o - OFF_TAILS)));
        v = make_float4((float)(N + b.x), (float)(N + b.y),
                        (float)(N + b.z), (float)(N + b.w));
    } else if (o < OFF_B) {
        // edge_attribute virtual-edge zeros
        v = make_float4(0.f, 0.f, 0.f, 0.f);
    } else if (o < OFF_B_AR) {
        // new_batch head = batch cast
        int4 b = ldcs4i((const int4*)(batch + (o - OFF_B)));
        v = make_float4((float)b.x, (float)b.y, (float)b.z, (float)b.w);
    } else {
        // new_batch tail = arange(B)
        float f = (float)(o - OFF_B_AR);
        v = make_float4(f, f + 1.f, f + 2.f, f + 3.f);
    }

    __stcs((float4*)(out + o), v);
}

extern "C" void kernel_launch(void* const* d_in, const int* in_sizes, int n_in,
                              void* d_out, int out_size) {
    const float* x     = (const float*)d_in[0];
    const int*   ei    = (const int*)d_in[1];
    const float* ea    = (const float*)d_in[2];
    const int*   batch = (const int*)d_in[3];
    float* out = (float*)d_out;

    const int T = 256;
    long long n4 = OFF_END / 4;  // 34,483,224 chunks
    unsigned blocks = (unsigned)((n4 + T - 1) / T);
    vnode_fused_kernel<<<blocks, T>>>(x, ei, ea, batch, out, (long long)out_size);
}

// round 4
// speedup vs baseline: 1.0897x; 1.0288x over previous
#include <cuda_runtime.h>
#include <cstdint>

// Problem constants (fixed shapes from reference)
static constexpr long long N  = 100000;   // nodes
static constexpr long long E  = 3200000;  // edges
static constexpr long long D  = 256;      // node feat
static constexpr long long De = 32;       // edge feat
static constexpr long long B  = 128;      // graphs

// Output layout (float32 units), concatenation of flattened outputs:
// new_x [N+B, D] | new_edge_index [2, E+N] | new_edge_attribute [E+N, De] | new_batch [N+B]
static constexpr long long OFF_X       = 0;
static constexpr long long OFF_X_ZERO  = OFF_X + N * D;                 // 25,600,000
static constexpr long long OFF_EI      = OFF_X + (N + B) * D;           // 25,632,768
static constexpr long long OFF_EI_R0   = OFF_EI;
static constexpr long long OFF_HEADS   = OFF_EI_R0 + E;                 // 28,832,768
static constexpr long long OFF_EI_R1   = OFF_EI + (E + N);              // 28,932,768
static constexpr long long OFF_TAILS   = OFF_EI_R1 + E;                 // 32,132,768
static constexpr long long OFF_EA      = OFF_EI + 2 * (E + N);          // 32,232,768
static constexpr long long OFF_EA_ZERO = OFF_EA + E * De;               // 134,632,768
static constexpr long long OFF_B       = OFF_EA + (E + N) * De;         // 137,832,768
static constexpr long long OFF_B_AR    = OFF_B + N;                     // 137,932,768
static constexpr long long OFF_END     = OFF_B_AR + B;                  // 137,932,896

static constexpr int UNROLL = 4;

// All region boundaries are multiples of 4 floats, so every 16B output chunk
// falls entirely within one region. Single fused kernel, 4 independent chunks
// per thread (front-batched LDG.128s -> MLP_p1~4), streaming cache hints.

__device__ __forceinline__ float4 region_value(
    long long o,
    const float* __restrict__ x, const int* __restrict__ ei,
    const float* __restrict__ ea, const int* __restrict__ batch)
{
    float4 v;
    if (o >= OFF_EA && o < OFF_EA_ZERO) {
        // edge_attribute copy (77% of all chunks)
        v = __ldcs((const float4*)(ea + (o - OFF_EA)));
    } else if (o < OFF_X_ZERO) {
        // x copy (18.6%)
        v = __ldcs((const float4*)(x + o));
    } else if (o < OFF_EI) {
        v = make_float4(0.f, 0.f, 0.f, 0.f);          // x virtual-node zeros
    } else if (o < OFF_HEADS) {
        int4 a = __ldcs((const int4*)(ei + (o - OFF_EI_R0)));
        v = make_float4((float)a.x, (float)a.y, (float)a.z, (float)a.w);
    } else if (o < OFF_EI_R1) {
        float f = (float)(o - OFF_HEADS);              // heads = arange(N)
        v = make_float4(f, f + 1.f, f + 2.f, f + 3.f);
    } else if (o < OFF_TAILS) {
        int4 a = __ldcs((const int4*)(ei + E + (o - OFF_EI_R1)));
        v = make_float4((float)a.x, (float)a.y, (float)a.z, (float)a.w);
    } else if (o < OFF_EA) {
        int4 b = __ldcs((const int4*)(batch + (o - OFF_TAILS)));
        v = make_float4((float)(N + b.x), (float)(N + b.y),
                        (float)(N + b.z), (float)(N + b.w));
    } else if (o < OFF_B) {
        v = make_float4(0.f, 0.f, 0.f, 0.f);          // edge_attr virtual zeros
    } else if (o < OFF_B_AR) {
        int4 b = __ldcs((const int4*)(batch + (o - OFF_B)));
        v = make_float4((float)b.x, (float)b.y, (float)b.z, (float)b.w);
    } else {
        float f = (float)(o - OFF_B_AR);               // arange(B)
        v = make_float4(f, f + 1.f, f + 2.f, f + 3.f);
    }
    return v;
}

__global__ void __launch_bounds__(256) vnode_fused_kernel(
    const float* __restrict__ x, const int* __restrict__ ei,
    const float* __restrict__ ea, const int* __restrict__ batch,
    float* __restrict__ out, long long out_lim)
{
    const long long stride = (long long)gridDim.x * blockDim.x;
    const long long i0 = (long long)blockIdx.x * blockDim.x + threadIdx.x;
    const long long n4 = OFF_END / 4;
    const long long lim = out_lim < OFF_END ? out_lim : OFF_END;

    long long o[UNROLL];
    bool ok[UNROLL];
    float4 v[UNROLL];

#pragma unroll
    for (int k = 0; k < UNROLL; k++) {
        long long i = i0 + (long long)k * stride;
        o[k] = 4 * i;
        ok[k] = (i < n4) && (o[k] + 3 < lim);
    }
#pragma unroll
    for (int k = 0; k < UNROLL; k++) {
        if (ok[k]) v[k] = region_value(o[k], x, ei, ea, batch);
    }
#pragma unroll
    for (int k = 0; k < UNROLL; k++) {
        if (ok[k]) __stcs((float4*)(out + o[k]), v[k]);
    }
}

extern "C" void kernel_launch(void* const* d_in, const int* in_sizes, int n_in,
                              void* d_out, int out_size) {
    const float* x     = (const float*)d_in[0];
    const int*   ei    = (const int*)d_in[1];
    const float* ea    = (const float*)d_in[2];
    const int*   batch = (const int*)d_in[3];
    float* out = (float*)d_out;

    const int T = 256;
    long long n4 = OFF_END / 4;  // 34,483,224 chunks
    long long per_grid = (long long)T * UNROLL;
    unsigned blocks = (unsigned)((n4 + per_grid - 1) / per_grid);
    vnode_fused_kernel<<<blocks, T>>>(x, ei, ea, batch, out, (long long)out_size);
}